// round 3
// baseline (speedup 1.0000x reference)
#include <cuda_runtime.h>
#include <math.h>

// ---------------------------------------------------------------------------
// BiLSTM: B=32, T=512, D=512, H=512.
//   Kernel 0: transpose x[b][t][d] -> g_xT[t][d][b]
//   Kernel 1: xg[dir][t][g][b] = sum_d x*W_ih + b_ih + b_hh     (unchanged)
//   Kernel 2: persistent recurrence, 128 blocks x 128 threads:
//             f32x2 FMA, 8 rows/thread, flag-array barrier per direction
// ---------------------------------------------------------------------------

#define BB 32
#define TT 512
#define DD 512
#define HH 512
#define G4 2048
#define NBLK 128

typedef unsigned long long ull;

// Scratch (device globals; no allocation allowed)
__device__ float g_xT[(size_t)TT * DD * BB];              // [t][d][b]
__device__ float g_xg[(size_t)2 * TT * G4 * BB];          // [dir][t][g][b]
__device__ float g_hp[2 * 2 * 256 * 32 * 2];              // [buf][dir][k2][b][pair]
__device__ int   g_flags[NBLK];

__device__ __forceinline__ float sigmoidf_(float x) {
    return 1.0f / (1.0f + expf(-x));
}

__device__ __forceinline__ ull ffma2(ull a, ull b, ull c) {
    ull d;
    asm("fma.rn.f32x2 %0, %1, %2, %3;" : "=l"(d) : "l"(a), "l"(b), "l"(c));
    return d;
}
__device__ __forceinline__ float sum2(ull v) {
    float a, b;
    asm("mov.b64 {%0, %1}, %2;" : "=f"(a), "=f"(b) : "l"(v));
    return a + b;
}

// ---------------------------------------------------------------------------
// init: reset flags + zero h buffers (graph replays)
// ---------------------------------------------------------------------------
__global__ void init_kernel() {
    int i = blockIdx.x * blockDim.x + threadIdx.x;
    if (i < NBLK) g_flags[i] = 0;
    if (i < 2 * 2 * 256 * 32 * 2) g_hp[i] = 0.f;
}

// ---------------------------------------------------------------------------
// Kernel 0: transpose x[b][t][d] -> g_xT[t][d][b]   (unchanged, passing)
// ---------------------------------------------------------------------------
__global__ void transpose_x(const float* __restrict__ x) {
    int t = blockIdx.x;
    int d0 = blockIdx.y * 32;
    __shared__ float tile[32][33];
    int tid = threadIdx.x;
    {
        int b = tid >> 3;
        int dq = (tid & 7) * 4;
        float4 v = *(const float4*)(x + ((size_t)(b * TT + t)) * DD + d0 + dq);
        tile[b][dq + 0] = v.x; tile[b][dq + 1] = v.y;
        tile[b][dq + 2] = v.z; tile[b][dq + 3] = v.w;
    }
    __syncthreads();
    {
        int d = tid >> 3;
        int bq = (tid & 7) * 4;
        float4 o;
        o.x = tile[bq + 0][d]; o.y = tile[bq + 1][d];
        o.z = tile[bq + 2][d]; o.w = tile[bq + 3][d];
        *(float4*)(g_xT + ((size_t)(t * DD + d0 + d)) * 32 + bq) = o;
    }
}

// ---------------------------------------------------------------------------
// Kernel 1: xg precompute (unchanged, passing)
// ---------------------------------------------------------------------------
__device__ __forceinline__ void dot4(const float* __restrict__ sW,
                                     const float* __restrict__ sV,
                                     int w, int lane, float a[4]) {
    const float* w0 = sW + (size_t)(w     ) * 512;
    const float* w1 = sW + (size_t)(w +  8) * 512;
    const float* w2 = sW + (size_t)(w + 16) * 512;
    const float* w3 = sW + (size_t)(w + 24) * 512;
    float a0 = 0.f, a1 = 0.f, a2 = 0.f, a3 = 0.f;
#pragma unroll 4
    for (int k = 0; k < 512; k += 4) {
        float4 v0 = *(const float4*)(w0 + k);
        float4 v1 = *(const float4*)(w1 + k);
        float4 v2 = *(const float4*)(w2 + k);
        float4 v3 = *(const float4*)(w3 + k);
        float h0 = sV[(k + 0) * 32 + lane];
        float h1 = sV[(k + 1) * 32 + lane];
        float h2 = sV[(k + 2) * 32 + lane];
        float h3 = sV[(k + 3) * 32 + lane];
        a0 = fmaf(v0.x, h0, a0); a0 = fmaf(v0.y, h1, a0);
        a0 = fmaf(v0.z, h2, a0); a0 = fmaf(v0.w, h3, a0);
        a1 = fmaf(v1.x, h0, a1); a1 = fmaf(v1.y, h1, a1);
        a1 = fmaf(v1.z, h2, a1); a1 = fmaf(v1.w, h3, a1);
        a2 = fmaf(v2.x, h0, a2); a2 = fmaf(v2.y, h1, a2);
        a2 = fmaf(v2.z, h2, a2); a2 = fmaf(v2.w, h3, a2);
        a3 = fmaf(v3.x, h0, a3); a3 = fmaf(v3.y, h1, a3);
        a3 = fmaf(v3.z, h2, a3); a3 = fmaf(v3.w, h3, a3);
    }
    a[0] = a0; a[1] = a1; a[2] = a2; a[3] = a3;
}

__global__ void __launch_bounds__(256, 1)
xg_kernel(const float* __restrict__ Wihf, const float* __restrict__ Wihb,
          const float* __restrict__ bihf, const float* __restrict__ bhhf,
          const float* __restrict__ bihb, const float* __restrict__ bhhb) {
    extern __shared__ float smem[];
    float* sW = smem;              // 32*512
    float* sX = smem + 32 * 512;   // 512*32
    int t = blockIdx.x;
    int ry = blockIdx.y;
    int dir = ry >> 6;
    int gbase = (ry & 63) * 32;
    const float* Wih = dir ? Wihb : Wihf;
    const float* bih = dir ? bihb : bihf;
    const float* bhh = dir ? bhhb : bhhf;
    int tid = threadIdx.x;
    {
        const float4* src = (const float4*)(Wih + (size_t)gbase * DD);
        float4* dst = (float4*)sW;
        for (int i = tid; i < 32 * 128; i += 256) dst[i] = src[i];
    }
    {
        const float4* src = (const float4*)(g_xT + (size_t)t * DD * 32);
        float4* dst = (float4*)sX;
        for (int i = tid; i < 4096; i += 256) dst[i] = src[i];
    }
    __syncthreads();
    int w = tid >> 5, lane = tid & 31;
    float a[4];
    dot4(sW, sX, w, lane, a);
    float* outp = g_xg + (((size_t)dir * TT + t) * G4 + gbase) * 32;
#pragma unroll
    for (int q = 0; q < 4; q++) {
        int r = q * 8 + w;
        int g = gbase + r;
        outp[(size_t)r * 32 + lane] = a[q] + bih[g] + bhh[g];
    }
}

// ---------------------------------------------------------------------------
// Kernel 2: persistent recurrence.
// 128 blocks x 128 threads. Block = (dir, 8 units = 32 gate rows).
// Warp w owns units {2w, 2w+1} (all 4 gates each); lane = batch.
// 8 f32x2 accumulators per thread; W_hh slice resident in smem for all steps.
// h double buffer in L2 as [buf][dir][k2][b][pair]; per-direction flag barrier.
// smem: sW 64KB + sH 64KB = 128KB -> 1 block/SM -> 128 blocks co-resident.
// ---------------------------------------------------------------------------
__global__ void __launch_bounds__(128, 1)
rec_kernel(const float* __restrict__ Whhf, const float* __restrict__ Whhb,
           const int* __restrict__ lengths, float* __restrict__ out) {
    extern __shared__ float smem[];
    float* sW = smem;                       // 32 rows x 512
    ull*   sH = (ull*)(smem + 32 * 512);    // 256 k2 x 32 b (f32x2 pairs)

    int blk = blockIdx.x;
    int dir = blk >> 6;
    int jbase = (blk & 63) * 8;
    int tid = threadIdx.x, w = tid >> 5, lane = tid & 31;
    const float* Whh = dir ? Whhb : Whhf;

    // Load W_hh slice once: local row r = g*8 + uu  ->  global row g*512 + jbase + uu
    for (int i = tid; i < 32 * 128; i += 128) {
        int r = i >> 7, c4 = i & 127;
        int g = r >> 3, uu = r & 7;
        ((float4*)sW)[i] = ((const float4*)Whh)[(size_t)(g * HH + jbase + uu) * 128 + c4];
    }

    int mylen = lengths[lane];
    int j0 = jbase + 2 * w;                 // first of this thread's two units
    float c0 = 0.f, h0 = 0.f, c1 = 0.f, h1 = 0.f;
    const float* xgd = g_xg + (size_t)dir * TT * G4 * 32;

    for (int s = 0; s < TT; s++) {
        int t = dir ? (TT - 1 - s) : s;
        int buf = s & 1;

        // xg loads (DRAM stream) issued first to overlap with copy + dot
        const float* xgt = xgd + (size_t)t * G4 * 32;
        float xv[8];
#pragma unroll
        for (int g = 0; g < 4; g++) {
            xv[g * 2 + 0] = __ldcs(xgt + (size_t)(g * HH + j0    ) * 32 + lane);
            xv[g * 2 + 1] = __ldcs(xgt + (size_t)(g * HH + j0 + 1) * 32 + lane);
        }

        // stage h (previous step, L2) into smem — __ldcg: L2-coherent, no stale L1
        {
            const float4* src = (const float4*)(g_hp + (size_t)(buf * 2 + dir) * 16384);
            float4* dst = (float4*)sH;
#pragma unroll
            for (int i = 0; i < 32; i++) dst[tid + i * 128] = __ldcg(src + tid + i * 128);
        }
        __syncthreads();

        // dot: 8 rows x f32x2 over K
        ull acc[8];
#pragma unroll
        for (int q = 0; q < 8; q++) acc[q] = 0ull;
#pragma unroll 4
        for (int k2 = 0; k2 < 256; k2 += 2) {
            ull hp0 = sH[(k2    ) * 32 + lane];
            ull hp1 = sH[(k2 + 1) * 32 + lane];
#pragma unroll
            for (int g = 0; g < 4; g++) {
                int r = g * 8 + 2 * w;
                ulonglong2 wa = *(const ulonglong2*)(sW + (size_t)(r    ) * 512 + 2 * k2);
                ulonglong2 wb = *(const ulonglong2*)(sW + (size_t)(r + 1) * 512 + 2 * k2);
                acc[g * 2 + 0] = ffma2(wa.x, hp0, acc[g * 2 + 0]);
                acc[g * 2 + 0] = ffma2(wa.y, hp1, acc[g * 2 + 0]);
                acc[g * 2 + 1] = ffma2(wb.x, hp0, acc[g * 2 + 1]);
                acc[g * 2 + 1] = ffma2(wb.y, hp1, acc[g * 2 + 1]);
            }
        }

        // pointwise for both units
        bool upd = (t < mylen);
        {
            float gi = sigmoidf_(sum2(acc[0]) + xv[0]);
            float gf = sigmoidf_(sum2(acc[2]) + xv[2]);
            float gg = tanhf   (sum2(acc[4]) + xv[4]);
            float go = sigmoidf_(sum2(acc[6]) + xv[6]);
            float cn = gf * c0 + gi * gg;
            float hn = go * tanhf(cn);
            if (upd) { c0 = cn; h0 = hn; }
        }
        {
            float gi = sigmoidf_(sum2(acc[1]) + xv[1]);
            float gf = sigmoidf_(sum2(acc[3]) + xv[3]);
            float gg = tanhf   (sum2(acc[5]) + xv[5]);
            float go = sigmoidf_(sum2(acc[7]) + xv[7]);
            float cn = gf * c1 + gi * gg;
            float hn = go * tanhf(cn);
            if (upd) { c1 = cn; h1 = hn; }
        }

        // publish h pair for next step (units 2w, 2w+1 are one f32x2 pair)
        {
            float2 hv = make_float2(h0, h1);
            float* dstp = g_hp + (size_t)((buf ^ 1) * 2 + dir) * 16384
                               + ((size_t)(jbase / 2 + w) * 32 + lane) * 2;
            __stcg((float2*)dstp, hv);
            // output: out[b][t][dir*H + j0 .. j0+1]
            *(float2*)(out + ((size_t)lane * TT + t) * 1024 + dir * HH + j0) = hv;
        }

        // flag-array barrier, per direction
        __threadfence();
        __syncthreads();
        if (tid == 0) ((volatile int*)g_flags)[blk] = s + 1;
        if (tid < 64) {
            volatile int* f = (volatile int*)&g_flags[dir * 64 + tid];
            while (*f < s + 1) { }
        }
        __syncthreads();
    }
}

// ---------------------------------------------------------------------------
// Launch
// ---------------------------------------------------------------------------
extern "C" void kernel_launch(void* const* d_in, const int* in_sizes, int n_in,
                              void* d_out, int out_size) {
    const float* x      = (const float*)d_in[0];
    const int*   lens   = (const int*)  d_in[1];
    const float* W_ih_f = (const float*)d_in[2];
    const float* W_hh_f = (const float*)d_in[3];
    const float* b_ih_f = (const float*)d_in[4];
    const float* b_hh_f = (const float*)d_in[5];
    const float* W_ih_b = (const float*)d_in[6];
    const float* W_hh_b = (const float*)d_in[7];
    const float* b_ih_b = (const float*)d_in[8];
    const float* b_hh_b = (const float*)d_in[9];
    float* out = (float*)d_out;

    cudaFuncSetAttribute(xg_kernel,  cudaFuncAttributeMaxDynamicSharedMemorySize, 131072);
    cudaFuncSetAttribute(rec_kernel, cudaFuncAttributeMaxDynamicSharedMemorySize, 131072);

    init_kernel<<<256, 256>>>();
    transpose_x<<<dim3(TT, DD / 32), 256>>>(x);
    xg_kernel<<<dim3(TT, 128), 256, 131072>>>(W_ih_f, W_ih_b, b_ih_f, b_hh_f, b_ih_b, b_hh_b);
    rec_kernel<<<NBLK, 128, 131072>>>(W_hh_f, W_hh_b, lens, out);
}

// round 4
// speedup vs baseline: 1.2955x; 1.2955x over previous
#include <cuda_runtime.h>
#include <math.h>
#include <stdint.h>

// ---------------------------------------------------------------------------
// BiLSTM: B=32, T=512, D=512, H=512.
//   K0: transpose x[b][t][d] -> g_xT[t][d][b]
//   K1: xg precompute, W-tile resident over 8 timesteps, cp.async x tiles
//   K2: persistent recurrence, 128 blocks x 256 threads, f32x2,
//       chunk-pipelined h copy, flag-array barrier per direction
// ---------------------------------------------------------------------------

#define BB 32
#define TT 512
#define DD 512
#define HH 512
#define G4 2048
#define NBLK 128

typedef unsigned long long ull;

__device__ float g_xT[(size_t)TT * DD * BB];      // [t][d][b]
__device__ float g_xg[(size_t)2 * TT * G4 * BB];  // [dir][t][g][b]
// h pair layout: float idx = (j>>2)*128 + lane*4 + (j&3)  (== ull[k4][lane][2])
__device__ float g_hp[2 * 2 * 16384];             // [buf][dir][...]
__device__ int   g_flags[NBLK];

__device__ __forceinline__ float sigmoidf_(float x) {
    return 1.0f / (1.0f + expf(-x));
}
__device__ __forceinline__ ull ffma2(ull a, ull b, ull c) {
    ull d;
    asm("fma.rn.f32x2 %0, %1, %2, %3;" : "=l"(d) : "l"(a), "l"(b), "l"(c));
    return d;
}
__device__ __forceinline__ float sum2(ull v) {
    float a, b;
    asm("mov.b64 {%0, %1}, %2;" : "=f"(a), "=f"(b) : "l"(v));
    return a + b;
}
__device__ __forceinline__ void cpa16(uint32_t s, const void* g) {
    asm volatile("cp.async.cg.shared.global [%0], [%1], 16;" :: "r"(s), "l"(g));
}
__device__ __forceinline__ void cpa_commit() {
    asm volatile("cp.async.commit_group;");
}
template <int N> __device__ __forceinline__ void cpa_wait() {
    asm volatile("cp.async.wait_group %0;" :: "n"(N));
}

// ---------------------------------------------------------------------------
__global__ void init_kernel() {
    int i = blockIdx.x * blockDim.x + threadIdx.x;
    if (i < NBLK) g_flags[i] = 0;
    if (i < 2 * 2 * 16384) g_hp[i] = 0.f;
}

// ---------------------------------------------------------------------------
// K0: transpose (unchanged, passing)
// ---------------------------------------------------------------------------
__global__ void transpose_x(const float* __restrict__ x) {
    int t = blockIdx.x;
    int d0 = blockIdx.y * 32;
    __shared__ float tile[32][33];
    int tid = threadIdx.x;
    {
        int b = tid >> 3;
        int dq = (tid & 7) * 4;
        float4 v = *(const float4*)(x + ((size_t)(b * TT + t)) * DD + d0 + dq);
        tile[b][dq + 0] = v.x; tile[b][dq + 1] = v.y;
        tile[b][dq + 2] = v.z; tile[b][dq + 3] = v.w;
    }
    __syncthreads();
    {
        int d = tid >> 3;
        int bq = (tid & 7) * 4;
        float4 o;
        o.x = tile[bq + 0][d]; o.y = tile[bq + 1][d];
        o.z = tile[bq + 2][d]; o.w = tile[bq + 3][d];
        *(float4*)(g_xT + ((size_t)(t * DD + d0 + d)) * 32 + bq) = o;
    }
}

// ---------------------------------------------------------------------------
// scalar 4-row dot (W broadcast, h per-lane)
// ---------------------------------------------------------------------------
__device__ __forceinline__ void dot4(const float* __restrict__ sW,
                                     const float* __restrict__ sV,
                                     int w, int lane, float a[4]) {
    const float* w0 = sW + (size_t)(w     ) * 512;
    const float* w1 = sW + (size_t)(w +  8) * 512;
    const float* w2 = sW + (size_t)(w + 16) * 512;
    const float* w3 = sW + (size_t)(w + 24) * 512;
    float a0 = 0.f, a1 = 0.f, a2 = 0.f, a3 = 0.f;
#pragma unroll 4
    for (int k = 0; k < 512; k += 4) {
        float4 v0 = *(const float4*)(w0 + k);
        float4 v1 = *(const float4*)(w1 + k);
        float4 v2 = *(const float4*)(w2 + k);
        float4 v3 = *(const float4*)(w3 + k);
        float h0 = sV[(k + 0) * 32 + lane];
        float h1 = sV[(k + 1) * 32 + lane];
        float h2 = sV[(k + 2) * 32 + lane];
        float h3 = sV[(k + 3) * 32 + lane];
        a0 = fmaf(v0.x, h0, a0); a0 = fmaf(v0.y, h1, a0);
        a0 = fmaf(v0.z, h2, a0); a0 = fmaf(v0.w, h3, a0);
        a1 = fmaf(v1.x, h0, a1); a1 = fmaf(v1.y, h1, a1);
        a1 = fmaf(v1.z, h2, a1); a1 = fmaf(v1.w, h3, a1);
        a2 = fmaf(v2.x, h0, a2); a2 = fmaf(v2.y, h1, a2);
        a2 = fmaf(v2.z, h2, a2); a2 = fmaf(v2.w, h3, a2);
        a3 = fmaf(v3.x, h0, a3); a3 = fmaf(v3.y, h1, a3);
        a3 = fmaf(v3.z, h2, a3); a3 = fmaf(v3.w, h3, a3);
    }
    a[0] = a0; a[1] = a1; a[2] = a2; a[3] = a3;
}

// ---------------------------------------------------------------------------
// K1: xg precompute. grid (64 tchunks, 128 tiles). Block: W tile resident,
// loops 8 timesteps with cp.async double-buffered x tiles.
// smem: sW 64KB + sX[2] 128KB = 192KB
// ---------------------------------------------------------------------------
__global__ void __launch_bounds__(256, 1)
xg_kernel(const float* __restrict__ Wihf, const float* __restrict__ Wihb,
          const float* __restrict__ bihf, const float* __restrict__ bhhf,
          const float* __restrict__ bihb, const float* __restrict__ bhhb) {
    extern __shared__ float smem[];
    float* sW = smem;                         // 32 x 512
    float* sX0 = smem + 16384;                // 512 x 32
    float* sX1 = smem + 32768;

    int tc = blockIdx.x;                      // 8-timestep chunk
    int ry = blockIdx.y;
    int dir = ry >> 6;
    int gbase = (ry & 63) * 32;
    const float* Wih = dir ? Wihb : Wihf;
    const float* bih = dir ? bihb : bihf;
    const float* bhh = dir ? bhhb : bhhf;
    int tid = threadIdx.x, w = tid >> 5, lane = tid & 31;

    {   // W tile
        const float4* src = (const float4*)(Wih + (size_t)gbase * DD);
        float4* dst = (float4*)sW;
        for (int i = tid; i < 32 * 128; i += 256) dst[i] = src[i];
    }
    // bias per thread's 4 rows
    float bias[4];
#pragma unroll
    for (int q = 0; q < 4; q++) {
        int g = gbase + q * 8 + w;
        bias[q] = bih[g] + bhh[g];
    }

    uint32_t sx0a = (uint32_t)__cvta_generic_to_shared(sX0);
    uint32_t sx1a = (uint32_t)__cvta_generic_to_shared(sX1);

    int t0 = tc * 8;
    // prologue: issue x tile for it=0
    {
        const char* src = (const char*)(g_xT + (size_t)t0 * DD * 32);
#pragma unroll
        for (int i = 0; i < 16; i++)
            cpa16(sx0a + (tid + i * 256) * 16, src + (size_t)(tid + i * 256) * 16);
        cpa_commit();
    }
#pragma unroll 1
    for (int it = 0; it < 8; it++) {
        if (it < 7) {   // issue next tile into the other buffer
            uint32_t dsta = ((it + 1) & 1) ? sx1a : sx0a;
            const char* src = (const char*)(g_xT + (size_t)(t0 + it + 1) * DD * 32);
#pragma unroll
            for (int i = 0; i < 16; i++)
                cpa16(dsta + (tid + i * 256) * 16, src + (size_t)(tid + i * 256) * 16);
            cpa_commit();
            cpa_wait<1>();
        } else {
            cpa_wait<0>();
        }
        __syncthreads();

        const float* sX = (it & 1) ? sX1 : sX0;
        float a[4];
        dot4(sW, sX, w, lane, a);

        int t = t0 + it;
        float* outp = g_xg + (((size_t)dir * TT + t) * G4 + gbase) * 32;
#pragma unroll
        for (int q = 0; q < 4; q++) {
            int r = q * 8 + w;
            __stcs(outp + (size_t)r * 32 + lane, a[q] + bias[q]);
        }
        __syncthreads();   // all reads of current buffer done before reuse
    }
}

// ---------------------------------------------------------------------------
// K2: persistent recurrence. 128 blocks x 256 threads.
// Block = (dir, 8 units). Warp w owns unit j=jbase+w (rows w,8+w,16+w,24+w).
// lane = batch. f32x2 dot. h copy pipelined in 4 chunks. Flag barrier/dir.
// smem: sW 64KB + sH 64KB = 128KB
// ---------------------------------------------------------------------------
__global__ void __launch_bounds__(256, 1)
rec_kernel(const float* __restrict__ Whhf, const float* __restrict__ Whhb,
           const int* __restrict__ lengths, float* __restrict__ out) {
    extern __shared__ float smem[];
    float* sW = smem;                        // 32 rows x 512
    ull*   sHu = (ull*)(smem + 16384);       // [k4][lane][2] pairs
    __shared__ float sOut[32][8];

    int blk = blockIdx.x;
    int dir = blk >> 6;
    int jbase = (blk & 63) * 8;
    int tid = threadIdx.x, w = tid >> 5, lane = tid & 31;
    const float* Whh = dir ? Whhb : Whhf;

    // W_hh slice once: local row r=g*8+u -> global row g*512+jbase+u
    for (int i = tid; i < 32 * 128; i += 256) {
        int r = i >> 7, c4 = i & 127;
        int g = r >> 3, u = r & 7;
        ((float4*)sW)[i] = ((const float4*)Whh)[(size_t)(g * HH + jbase + u) * 128 + c4];
    }

    int mylen = lengths[lane];
    int j = jbase + w;
    float c = 0.f, h = 0.f;
    const float* xgd = g_xg + (size_t)dir * TT * G4 * 32;
    // publish address for this thread's h (pair layout)
    const int hoff = (j >> 2) * 128 + lane * 4 + (j & 3);
    // weight row base pointers (f32x2 pairs along k)
    const float* wr0 = sW + (size_t)(w     ) * 512;
    const float* wr1 = sW + (size_t)(w +  8) * 512;
    const float* wr2 = sW + (size_t)(w + 16) * 512;
    const float* wr3 = sW + (size_t)(w + 24) * 512;

    for (int s = 0; s < TT; s++) {
        int t = dir ? (TT - 1 - s) : s;
        int buf = s & 1;

        // xg prefetch (independent of barrier; DRAM latency hidden by dot)
        const float* xgt = xgd + (size_t)t * G4 * 32;
        float xv0 = __ldcs(xgt + (size_t)(0 * HH + j) * 32 + lane);
        float xv1 = __ldcs(xgt + (size_t)(1 * HH + j) * 32 + lane);
        float xv2 = __ldcs(xgt + (size_t)(2 * HH + j) * 32 + lane);
        float xv3 = __ldcs(xgt + (size_t)(3 * HH + j) * 32 + lane);

        const ulonglong2* hsrc =
            (const ulonglong2*)(g_hp + (size_t)(buf * 2 + dir) * 16384);

        ull acc0 = 0, acc1 = 0, acc2 = 0, acc3 = 0;

        // chunk 0 prefetch into regs
        ulonglong2 r0 = __ldcg(hsrc + tid + 0 * 256);
        ulonglong2 r1 = __ldcg(hsrc + tid + 1 * 256);
        ulonglong2 r2 = __ldcg(hsrc + tid + 2 * 256);
        ulonglong2 r3 = __ldcg(hsrc + tid + 3 * 256);

#pragma unroll
        for (int cch = 0; cch < 4; cch++) {
            // store chunk into smem
            ulonglong2* sdst = (ulonglong2*)sHu + cch * 1024;
            sdst[tid + 0 * 256] = r0;
            sdst[tid + 1 * 256] = r1;
            sdst[tid + 2 * 256] = r2;
            sdst[tid + 3 * 256] = r3;
            __syncthreads();
            // prefetch next chunk
            if (cch < 3) {
                r0 = __ldcg(hsrc + (cch + 1) * 1024 + tid + 0 * 256);
                r1 = __ldcg(hsrc + (cch + 1) * 1024 + tid + 1 * 256);
                r2 = __ldcg(hsrc + (cch + 1) * 1024 + tid + 2 * 256);
                r3 = __ldcg(hsrc + (cch + 1) * 1024 + tid + 3 * 256);
            }
            // dot over k4 in [cch*32, cch*32+32)
            int k4b = cch * 32;
#pragma unroll 4
            for (int k4 = k4b; k4 < k4b + 32; k4++) {
                ulonglong2 hp = *((const ulonglong2*)sHu + (size_t)k4 * 32 + lane);
                ulonglong2 wa = *(const ulonglong2*)(wr0 + 4 * k4);
                ulonglong2 wb = *(const ulonglong2*)(wr1 + 4 * k4);
                ulonglong2 wc = *(const ulonglong2*)(wr2 + 4 * k4);
                ulonglong2 wd = *(const ulonglong2*)(wr3 + 4 * k4);
                acc0 = ffma2(wa.x, hp.x, acc0); acc0 = ffma2(wa.y, hp.y, acc0);
                acc1 = ffma2(wb.x, hp.x, acc1); acc1 = ffma2(wb.y, hp.y, acc1);
                acc2 = ffma2(wc.x, hp.x, acc2); acc2 = ffma2(wc.y, hp.y, acc2);
                acc3 = ffma2(wd.x, hp.x, acc3); acc3 = ffma2(wd.y, hp.y, acc3);
            }
        }

        // pointwise
        {
            float gi = sigmoidf_(sum2(acc0) + xv0);
            float gf = sigmoidf_(sum2(acc1) + xv1);
            float gg = tanhf   (sum2(acc2) + xv2);
            float go = sigmoidf_(sum2(acc3) + xv3);
            float cn = gf * c + gi * gg;
            float hn = go * tanhf(cn);
            if (t < mylen) { c = cn; h = hn; }
        }

        // publish h for next step + stage output
        __stcg(g_hp + (size_t)((buf ^ 1) * 2 + dir) * 16384 + hoff, h);
        sOut[lane][w] = h;

        __threadfence();
        __syncthreads();
        if (tid == 0) ((volatile int*)g_flags)[blk] = s + 1;
        if (tid >= 64 && tid < 128) {
            int idx = tid - 64;
            int b = idx >> 1, half = idx & 1;
            float4 v;
            v.x = sOut[b][half * 4 + 0]; v.y = sOut[b][half * 4 + 1];
            v.z = sOut[b][half * 4 + 2]; v.w = sOut[b][half * 4 + 3];
            *(float4*)(out + ((size_t)(b * TT + t)) * 1024 + dir * HH + jbase + half * 4) = v;
        }
        if (tid < 64) {
            volatile int* f = (volatile int*)&g_flags[dir * 64 + tid];
            while (*f < s + 1) { }
        }
        __syncthreads();
    }
}

// ---------------------------------------------------------------------------
extern "C" void kernel_launch(void* const* d_in, const int* in_sizes, int n_in,
                              void* d_out, int out_size) {
    const float* x      = (const float*)d_in[0];
    const int*   lens   = (const int*)  d_in[1];
    const float* W_ih_f = (const float*)d_in[2];
    const float* W_hh_f = (const float*)d_in[3];
    const float* b_ih_f = (const float*)d_in[4];
    const float* b_hh_f = (const float*)d_in[5];
    const float* W_ih_b = (const float*)d_in[6];
    const float* W_hh_b = (const float*)d_in[7];
    const float* b_ih_b = (const float*)d_in[8];
    const float* b_hh_b = (const float*)d_in[9];
    float* out = (float*)d_out;

    cudaFuncSetAttribute(xg_kernel,  cudaFuncAttributeMaxDynamicSharedMemorySize, 196608);
    cudaFuncSetAttribute(rec_kernel, cudaFuncAttributeMaxDynamicSharedMemorySize, 131072);

    init_kernel<<<256, 256>>>();
    transpose_x<<<dim3(TT, DD / 32), 256>>>(x);
    xg_kernel<<<dim3(64, 128), 256, 196608>>>(W_ih_f, W_ih_b, b_ih_f, b_hh_f, b_ih_b, b_hh_b);
    rec_kernel<<<NBLK, 256, 131072>>>(W_hh_f, W_hh_b, lens, out);
}